// round 13
// baseline (speedup 1.0000x reference)
#include <cuda_runtime.h>
#include <cuda_fp16.h>
#include <mma.h>
#include <math.h>

using namespace nvcuda;

#define HEADS 8
#define OUTF 32
#define HF 256
#define IN_FEATS 256
#define NEG_SLOPE 0.2f
#define SCAN_CHUNK 4096
#define N_NODES_MAX 100000
#define N_EDGES_MAX 3200000
#define FULL 0xffffffffu

// ---------------- device scratch ----------------
__device__ __align__(16) __half g_hh[(size_t)N_NODES_MAX * HF];      // projected features, fp16
__device__ __align__(16) __half g_feat_h[(size_t)N_NODES_MAX * IN_FEATS]; // feat fp16
__device__ __align__(16) __half g_w_h[HF * IN_FEATS];                // weights fp16
__device__ float g_el[N_NODES_MAX * HEADS];
__device__ float g_er[N_NODES_MAX * HEADS];
__device__ int   g_cnt[N_NODES_MAX];          // zero at load; re-zeroed by scatter each call
__device__ int   g_row_off[N_NODES_MAX + 1];
__device__ int   g_rank[N_EDGES_MAX];         // edge rank within its dst segment
__device__ int   g_csr_src[N_EDGES_MAX];
__device__ int   g_blksum[64];
__device__ int   g_blkoff[64];

// ---------------- fp32 -> fp16 converters ----------------
__global__ void cvt_feat_kernel(const float* __restrict__ feat, int n8) {
    int i = blockIdx.x * blockDim.x + threadIdx.x;
    if (i >= n8) return;
    const float4* p = (const float4*)(feat + (size_t)i * 8);
    float4 a = p[0], b = p[1];
    __half2 h0 = __floats2half2_rn(a.x, a.y);
    __half2 h1 = __floats2half2_rn(a.z, a.w);
    __half2 h2 = __floats2half2_rn(b.x, b.y);
    __half2 h3 = __floats2half2_rn(b.z, b.w);
    uint4 pk;
    pk.x = *(unsigned*)&h0; pk.y = *(unsigned*)&h1;
    pk.z = *(unsigned*)&h2; pk.w = *(unsigned*)&h3;
    *(uint4*)(g_feat_h + (size_t)i * 8) = pk;
}

__global__ void cvt_w_kernel(const float* __restrict__ W) {
    int i = blockIdx.x * blockDim.x + threadIdx.x;   // HF*IN_FEATS/8 = 8192
    const float4* p = (const float4*)(W + (size_t)i * 8);
    float4 a = p[0], b = p[1];
    __half2 h0 = __floats2half2_rn(a.x, a.y);
    __half2 h1 = __floats2half2_rn(a.z, a.w);
    __half2 h2 = __floats2half2_rn(b.x, b.y);
    __half2 h3 = __floats2half2_rn(b.z, b.w);
    uint4 pk;
    pk.x = *(unsigned*)&h0; pk.y = *(unsigned*)&h1;
    pk.z = *(unsigned*)&h2; pk.w = *(unsigned*)&h3;
    *(uint4*)(g_w_h + (size_t)i * 8) = pk;
}

// ---------------- 1) HMMA GEMM (BM=128, BN=128, BK=32) + fused epilogue (round-11) ----------------
#define GEMM_SMEM_BYTES 73728

__global__ void __launch_bounds__(256) gemm_wmma_kernel(const float* __restrict__ attn_l,
                                                        const float* __restrict__ attn_r,
                                                        int M) {
    extern __shared__ char dynsmem[];
    __half* As = (__half*)dynsmem;            // [128][40]
    __half* Bs = As + 128 * 40;               // [128][40]
    float*  epi = (float*)dynsmem;            // reuse: [8][32][72]
    __shared__ float al_s[128], ar_s[128];

    const int m0 = blockIdx.x * 128;
    const int n0 = blockIdx.y * 128;
    const int tid = threadIdx.x;
    const int warp = tid >> 5;
    const int lane = tid & 31;
    const int wy = warp >> 1;   // 0..3 (m)
    const int wx = warp & 1;    // 0..1 (n)

    if (tid < 128) {
        al_s[tid] = attn_l[n0 + tid];
        ar_s[tid] = attn_r[n0 + tid];
    }

    const int idx0 = tid, idx1 = tid + 256;
    const int r0i = idx0 >> 2, q0 = idx0 & 3;
    const int r1i = idx1 >> 2, q1 = idx1 & 3;

    uint4 a0, a1, b0, b1;
    const uint4 zero4 = make_uint4(0, 0, 0, 0);

    {
        int gr0 = m0 + r0i, gr1 = m0 + r1i;
        a0 = (gr0 < M) ? *(const uint4*)(g_feat_h + (size_t)gr0 * IN_FEATS + q0 * 8) : zero4;
        a1 = (gr1 < M) ? *(const uint4*)(g_feat_h + (size_t)gr1 * IN_FEATS + q1 * 8) : zero4;
        b0 = *(const uint4*)(g_w_h + (size_t)(n0 + r0i) * IN_FEATS + q0 * 8);
        b1 = *(const uint4*)(g_w_h + (size_t)(n0 + r1i) * IN_FEATS + q1 * 8);
    }
    *(uint4*)(As + r0i * 40 + q0 * 8) = a0;
    *(uint4*)(As + r1i * 40 + q1 * 8) = a1;
    *(uint4*)(Bs + r0i * 40 + q0 * 8) = b0;
    *(uint4*)(Bs + r1i * 40 + q1 * 8) = b1;
    __syncthreads();

    wmma::fragment<wmma::accumulator, 16, 16, 16, float> acc[2][4];
#pragma unroll
    for (int i = 0; i < 2; i++)
#pragma unroll
        for (int j = 0; j < 4; j++) wmma::fill_fragment(acc[i][j], 0.0f);

#pragma unroll 1
    for (int k0 = 0; k0 < IN_FEATS; k0 += 32) {
        const bool more = (k0 + 32 < IN_FEATS);
        if (more) {
            int kn = k0 + 32;
            int gr0 = m0 + r0i, gr1 = m0 + r1i;
            a0 = (gr0 < M) ? *(const uint4*)(g_feat_h + (size_t)gr0 * IN_FEATS + kn + q0 * 8) : zero4;
            a1 = (gr1 < M) ? *(const uint4*)(g_feat_h + (size_t)gr1 * IN_FEATS + kn + q1 * 8) : zero4;
            b0 = *(const uint4*)(g_w_h + (size_t)(n0 + r0i) * IN_FEATS + kn + q0 * 8);
            b1 = *(const uint4*)(g_w_h + (size_t)(n0 + r1i) * IN_FEATS + kn + q1 * 8);
        }

#pragma unroll
        for (int ks = 0; ks < 32; ks += 16) {
            wmma::fragment<wmma::matrix_a, 16, 16, 16, __half, wmma::row_major> fa[2];
            wmma::fragment<wmma::matrix_b, 16, 16, 16, __half, wmma::col_major> fb[4];
#pragma unroll
            for (int i = 0; i < 2; i++)
                wmma::load_matrix_sync(fa[i], As + (wy * 32 + i * 16) * 40 + ks, 40);
#pragma unroll
            for (int j = 0; j < 4; j++)
                wmma::load_matrix_sync(fb[j], Bs + (wx * 64 + j * 16) * 40 + ks, 40);
#pragma unroll
            for (int i = 0; i < 2; i++)
#pragma unroll
                for (int j = 0; j < 4; j++)
                    wmma::mma_sync(acc[i][j], fa[i], fb[j], acc[i][j]);
        }
        __syncthreads();

        if (more) {
            *(uint4*)(As + r0i * 40 + q0 * 8) = a0;
            *(uint4*)(As + r1i * 40 + q1 * 8) = a1;
            *(uint4*)(Bs + r0i * 40 + q0 * 8) = b0;
            *(uint4*)(Bs + r1i * 40 + q1 * 8) = b1;
            __syncthreads();
        }
    }

    // all warps done reading As/Bs before the epilogue aliases that smem
    __syncthreads();

    float* ws = epi + warp * 32 * 72;
#pragma unroll
    for (int i = 0; i < 2; i++)
#pragma unroll
        for (int j = 0; j < 4; j++)
            wmma::store_matrix_sync(ws + i * 16 * 72 + j * 16, acc[i][j], 72, wmma::mem_row_major);
    __syncwarp();

    const int grow = m0 + wy * 32 + lane;
    const float* al = al_s + wx * 64;
    const float* ar = ar_s + wx * 64;
    const float* hr = ws + lane * 72;

    float el0 = 0.f, er0 = 0.f, el1 = 0.f, er1 = 0.f;
#pragma unroll
    for (int c = 0; c < 32; c++) {
        float v = hr[c];
        el0 = fmaf(v, al[c], el0);
        er0 = fmaf(v, ar[c], er0);
    }
#pragma unroll
    for (int c = 32; c < 64; c++) {
        float v = hr[c];
        el1 = fmaf(v, al[c], el1);
        er1 = fmaf(v, ar[c], er1);
    }

    if (grow < M) {
        __half* hrow = g_hh + (size_t)grow * HF + n0 + wx * 64;
#pragma unroll
        for (int c8 = 0; c8 < 8; c8++) {
            __half2 h0 = __floats2half2_rn(hr[c8 * 8 + 0], hr[c8 * 8 + 1]);
            __half2 h1 = __floats2half2_rn(hr[c8 * 8 + 2], hr[c8 * 8 + 3]);
            __half2 h2 = __floats2half2_rn(hr[c8 * 8 + 4], hr[c8 * 8 + 5]);
            __half2 h3 = __floats2half2_rn(hr[c8 * 8 + 6], hr[c8 * 8 + 7]);
            uint4 pk;
            pk.x = *(unsigned*)&h0; pk.y = *(unsigned*)&h1;
            pk.z = *(unsigned*)&h2; pk.w = *(unsigned*)&h3;
            *(uint4*)(hrow + c8 * 8) = pk;
        }
        int hb = (n0 + wx * 64) >> 5;
        g_el[(size_t)grow * HEADS + hb] = el0;
        g_el[(size_t)grow * HEADS + hb + 1] = el1;
        g_er[(size_t)grow * HEADS + hb] = er0;
        g_er[(size_t)grow * HEADS + hb + 1] = er1;
    }
}

// ---------------- 2) CSR build (rank-based, atomic-free scatter) ----------------
// hist: rank[i] = fetch-and-add of cnt[dst[i]]  (cnt starts zeroed)
__global__ void hist_kernel(const int* __restrict__ dst, int E) {
    int i = (blockIdx.x * blockDim.x + threadIdx.x) * 4;
    if (i + 4 <= E) {
        int4 d = __ldcs((const int4*)(dst + i));
        int4 r;
        r.x = atomicAdd(&g_cnt[d.x], 1);
        r.y = atomicAdd(&g_cnt[d.y], 1);
        r.z = atomicAdd(&g_cnt[d.z], 1);
        r.w = atomicAdd(&g_cnt[d.w], 1);
        *(int4*)(g_rank + i) = r;
    } else {
        for (int k = i; k < E; k++) g_rank[k] = atomicAdd(&g_cnt[dst[k]], 1);
    }
}

__global__ void __launch_bounds__(512) partial_sum_kernel(int N) {
    __shared__ int wsum[16];
    int b = blockIdx.x, tid = threadIdx.x;
    int base = b * SCAN_CHUNK + tid * 8;
    int s = 0;
    if (base + 8 <= N) {
        int4 a = *(const int4*)(g_cnt + base);
        int4 c = *(const int4*)(g_cnt + base + 4);
        s = a.x + a.y + a.z + a.w + c.x + c.y + c.z + c.w;
    } else {
#pragma unroll
        for (int k = 0; k < 8; k++) { int i = base + k; if (i < N) s += g_cnt[i]; }
    }
    int lane = tid & 31, wid = tid >> 5;
#pragma unroll
    for (int d = 16; d > 0; d >>= 1) s += __shfl_xor_sync(FULL, s, d);
    if (lane == 0) wsum[wid] = s;
    __syncthreads();
    if (wid == 0) {
        int w = (lane < 16) ? wsum[lane] : 0;
#pragma unroll
        for (int d = 16; d > 0; d >>= 1) w += __shfl_xor_sync(FULL, w, d);
        if (lane == 0) g_blksum[b] = w;
    }
}

__global__ void scan_blk_kernel(int nb, int E, int N) {
    int lane = threadIdx.x;
    int v = (lane < nb) ? g_blksum[lane] : 0;
    int x = v;
#pragma unroll
    for (int d = 1; d < 32; d <<= 1) {
        int y = __shfl_up_sync(FULL, x, d);
        if (lane >= d) x += y;
    }
    if (lane < nb) g_blkoff[lane] = x - v;
    if (lane == 0) g_row_off[N] = E;
}

__global__ void __launch_bounds__(512) scan_final_kernel(int N) {
    __shared__ int wsum[16];
    __shared__ int blk_base;
    int b = blockIdx.x, tid = threadIdx.x;
    int lane = tid & 31, wid = tid >> 5;
    if (tid == 0) blk_base = g_blkoff[b];

    int base = b * SCAN_CHUNK + tid * 8;
    int v[8];
#pragma unroll
    for (int k = 0; k < 8; k++) { int i = base + k; v[k] = (i < N) ? g_cnt[i] : 0; }
    int tot = 0;
#pragma unroll
    for (int k = 0; k < 8; k++) { int t = v[k]; v[k] = tot; tot += t; }

    int x = tot;
#pragma unroll
    for (int d = 1; d < 32; d <<= 1) {
        int y = __shfl_up_sync(FULL, x, d);
        if (lane >= d) x += y;
    }
    if (lane == 31) wsum[wid] = x;
    __syncthreads();
    if (wid == 0) {
        int w = (lane < 16) ? wsum[lane] : 0;
#pragma unroll
        for (int d = 1; d < 32; d <<= 1) {
            int y = __shfl_up_sync(FULL, w, d);
            if (lane >= d) w += y;
        }
        if (lane < 16) wsum[lane] = w;
    }
    __syncthreads();
    int toff = x - tot + ((wid > 0) ? wsum[wid - 1] : 0) + blk_base;
#pragma unroll
    for (int k = 0; k < 8; k++) {
        int i = base + k;
        if (i < N) g_row_off[i] = toff + v[k];
    }
}

// scatter: atomic-free (rank precomputed); also re-zeroes g_cnt for the next call
__global__ void scatter_kernel(const int* __restrict__ src,
                               const int* __restrict__ dst, int E, int N) {
    int t = blockIdx.x * blockDim.x + threadIdx.x;
    if (t < N) g_cnt[t] = 0;
    int i = t * 4;
    if (i + 4 <= E) {
        int4 s = __ldcs((const int4*)(src + i));
        int4 d = __ldcs((const int4*)(dst + i));
        int4 r = *(const int4*)(g_rank + i);
        g_csr_src[g_row_off[d.x] + r.x] = s.x;
        g_csr_src[g_row_off[d.y] + r.y] = s.y;
        g_csr_src[g_row_off[d.z] + r.z] = s.z;
        g_csr_src[g_row_off[d.w] + r.w] = s.w;
    } else {
        for (int k = i; k < E; k++)
            g_csr_src[g_row_off[dst[k]] + g_rank[k]] = src[k];
    }
}

// ---------------- 3) single-pass pipelined softmax + fp16 aggregation (round-11) ----------------
__global__ void __launch_bounds__(256) gat_agg_kernel(const float* __restrict__ bias,
                                                      float* __restrict__ out, int N) {
    int gwarp = (blockIdx.x * blockDim.x + threadIdx.x) >> 5;
    int lane = threadIdx.x & 31;
    if (gwarp >= N) return;

    const int n = gwarp;
    const int base = g_row_off[n];
    const int deg = g_row_off[n + 1] - base;

    float* orow = out + (size_t)n * HF;
    const float4* b4 = (const float4*)bias;
    float4 bv0 = b4[lane * 2], bv1 = b4[lane * 2 + 1];

    if (deg == 0) {
        __stcs((float4*)orow + lane * 2, bv0);
        __stcs((float4*)orow + lane * 2 + 1, bv1);
        return;
    }

    const int lane3 = lane & 3;
    const int hh = lane & 7;
    const int q = lane >> 3;
    const int gh = lane >> 2;
    const float er_h = __ldg(g_er + (size_t)n * HEADS + hh);

    float acc[8];
#pragma unroll
    for (int j = 0; j < 8; j++) acc[j] = 0.f;
    float smp = 0.f;

    int sj_c;
    {
        int i4 = lane3;
        sj_c = __ldcs(g_csr_src + base + ((i4 < deg) ? i4 : (deg - 1)));
    }
    float c_c;
    {
        int sq = __shfl_sync(FULL, sj_c, q);
        float e = __ldg(g_el + (size_t)sq * HEADS + hh) + er_h;
        e = (e > 0.f) ? e : NEG_SLOPE * e;
        c_c = (q < deg) ? __expf(e) : 0.f;
    }

    for (int j = 0; j < deg; j += 4) {
        const int jn = j + 4;
        const bool more = jn < deg;

        int sj_n = 0;
        if (more) {
            int i4 = jn + lane3;
            sj_n = __ldcs(g_csr_src + base + ((i4 < deg) ? i4 : (deg - 1)));
        }

        int s0 = __shfl_sync(FULL, sj_c, 0);
        int s1 = __shfl_sync(FULL, sj_c, 1);
        int s2 = __shfl_sync(FULL, sj_c, 2);
        int s3 = __shfl_sync(FULL, sj_c, 3);
        float c0 = __shfl_sync(FULL, c_c, gh);
        float c1 = __shfl_sync(FULL, c_c, 8 + gh);
        float c2 = __shfl_sync(FULL, c_c, 16 + gh);
        float c3 = __shfl_sync(FULL, c_c, 24 + gh);
        smp += c_c;

        uint4 w0 = *((const uint4*)(g_hh + (size_t)s0 * HF) + lane);
        uint4 w1 = *((const uint4*)(g_hh + (size_t)s1 * HF) + lane);
        uint4 w2 = *((const uint4*)(g_hh + (size_t)s2 * HF) + lane);
        uint4 w3 = *((const uint4*)(g_hh + (size_t)s3 * HF) + lane);

        float c_n = 0.f;
        if (more) {
            int sqn = __shfl_sync(FULL, sj_n, q);
            float en = __ldg(g_el + (size_t)sqn * HEADS + hh) + er_h;
            en = (en > 0.f) ? en : NEG_SLOPE * en;
            c_n = ((jn + q) < deg) ? __expf(en) : 0.f;
        }

#define AGG_EDGE(W, C)                                                        \
        {                                                                     \
            float2 f0 = __half22float2(*(const __half2*)&(W).x);              \
            float2 f1 = __half22float2(*(const __half2*)&(W).y);              \
            float2 f2 = __half22float2(*(const __half2*)&(W).z);              \
            float2 f3 = __half22float2(*(const __half2*)&(W).w);              \
            acc[0] = fmaf(f0.x, (C), acc[0]); acc[1] = fmaf(f0.y, (C), acc[1]); \
            acc[2] = fmaf(f1.x, (C), acc[2]); acc[3] = fmaf(f1.y, (C), acc[3]); \
            acc[4] = fmaf(f2.x, (C), acc[4]); acc[5] = fmaf(f2.y, (C), acc[5]); \
            acc[6] = fmaf(f3.x, (C), acc[6]); acc[7] = fmaf(f3.y, (C), acc[7]); \
        }
        AGG_EDGE(w0, c0) AGG_EDGE(w1, c1) AGG_EDGE(w2, c2) AGG_EDGE(w3, c3)
#undef AGG_EDGE

        sj_c = sj_n;
        c_c = c_n;
    }

    smp += __shfl_xor_sync(FULL, smp, 8);
    smp += __shfl_xor_sync(FULL, smp, 16);
    float inv = 1.0f / smp;
    float cinv = __shfl_sync(FULL, inv, gh);

    __stcs((float4*)orow + lane * 2,
           make_float4(fmaf(acc[0], cinv, bv0.x), fmaf(acc[1], cinv, bv0.y),
                       fmaf(acc[2], cinv, bv0.z), fmaf(acc[3], cinv, bv0.w)));
    __stcs((float4*)orow + lane * 2 + 1,
           make_float4(fmaf(acc[4], cinv, bv1.x), fmaf(acc[5], cinv, bv1.y),
                       fmaf(acc[6], cinv, bv1.z), fmaf(acc[7], cinv, bv1.w)));
}

// ---------------- launch (fork-join; gemm is submission index 3 for ncu capture) ----------------
static cudaStream_t get_side_stream() {
    static cudaStream_t s = [] {
        cudaStream_t t;
        cudaStreamCreateWithFlags(&t, cudaStreamNonBlocking);
        return t;
    }();
    return s;
}
static cudaEvent_t get_ev(int which) {
    static cudaEvent_t e0 = [] {
        cudaEvent_t e; cudaEventCreateWithFlags(&e, cudaEventDisableTiming); return e;
    }();
    static cudaEvent_t e1 = [] {
        cudaEvent_t e; cudaEventCreateWithFlags(&e, cudaEventDisableTiming); return e;
    }();
    return which ? e1 : e0;
}

extern "C" void kernel_launch(void* const* d_in, const int* in_sizes, int n_in,
                              void* d_out, int out_size) {
    const float* feat   = (const float*)d_in[0];
    const int*   src    = (const int*)d_in[1];
    const int*   dst    = (const int*)d_in[2];
    const float* fc_w   = (const float*)d_in[3];
    const float* attn_l = (const float*)d_in[4];
    const float* attn_r = (const float*)d_in[5];
    const float* bias   = (const float*)d_in[6];
    float* out = (float*)d_out;

    const int M = in_sizes[0] / IN_FEATS;
    const int E = in_sizes[1];

    cudaFuncSetAttribute(gemm_wmma_kernel,
                         cudaFuncAttributeMaxDynamicSharedMemorySize, GEMM_SMEM_BYTES);

    cudaStream_t sB = get_side_stream();
    cudaEvent_t evF = get_ev(0), evJ = get_ev(1);

    cudaEventRecord(evF, 0);
    cudaStreamWaitEvent(sB, evF, 0);

    // [0] main: feat fp32->fp16
    int n8 = M * (IN_FEATS / 8);
    cvt_feat_kernel<<<(n8 + 255) / 256, 256>>>(feat, n8);
    // [1] main: weight fp32->fp16
    cvt_w_kernel<<<(HF * IN_FEATS / 8) / 256, 256>>>(fc_w);
    // [2] side: histogram + per-edge rank
    hist_kernel<<<(E / 4 + 255) / 256, 256, 0, sB>>>(dst, E);
    // [3] main: tensor-core GEMM + fused el/er  (ncu capture target)
    dim3 ggrid((M + 127) / 128, HF / 128);
    gemm_wmma_kernel<<<ggrid, 256, GEMM_SMEM_BYTES>>>(attn_l, attn_r, M);
    // [4..7] side: scan + atomic-free scatter (also re-zeroes g_cnt)
    int nb = (M + SCAN_CHUNK - 1) / SCAN_CHUNK;
    partial_sum_kernel<<<nb, 512, 0, sB>>>(M);
    scan_blk_kernel<<<1, 32, 0, sB>>>(nb, E, M);
    scan_final_kernel<<<nb, 512, 0, sB>>>(M);
    scatter_kernel<<<(E / 4 + 255) / 256, 256, 0, sB>>>(src, dst, E, M);

    cudaEventRecord(evJ, sB);
    cudaStreamWaitEvent(0, evJ, 0);

    // [8] main: fused softmax + aggregation
    int warp_blocks = (M * 32 + 255) / 256;
    gat_agg_kernel<<<warp_blocks, 256>>>(bias, out, M);
}

// round 14
// speedup vs baseline: 1.0418x; 1.0418x over previous
#include <cuda_runtime.h>
#include <cuda_fp16.h>
#include <mma.h>
#include <math.h>

using namespace nvcuda;

#define HEADS 8
#define OUTF 32
#define HF 256
#define IN_FEATS 256
#define NEG_SLOPE 0.2f
#define SCAN_CHUNK 4096
#define N_NODES_MAX 100000
#define N_EDGES_MAX 3200000
#define FULL 0xffffffffu

// ---------------- device scratch ----------------
__device__ __align__(16) __half g_hh[(size_t)N_NODES_MAX * HF];      // projected features, fp16
__device__ __align__(16) __half g_feat_h[(size_t)N_NODES_MAX * IN_FEATS]; // feat fp16
__device__ __align__(16) __half g_w_h[HF * IN_FEATS];                // weights fp16
__device__ float g_el[N_NODES_MAX * HEADS];
__device__ float g_er[N_NODES_MAX * HEADS];
__device__ int   g_cnt[N_NODES_MAX];          // zero at load; re-zeroed by scatter each call
__device__ int   g_row_off[N_NODES_MAX + 1];
__device__ int   g_rank[N_EDGES_MAX];         // edge rank within its dst segment
__device__ int   g_csr_src[N_EDGES_MAX];
__device__ int   g_blksum[64];
__device__ int   g_blkoff[64];

// ---------------- fused fp32 -> fp16 converter (feat then weights) ----------------
__global__ void cvt_all_kernel(const float* __restrict__ feat,
                               const float* __restrict__ W, int n8feat) {
    int i = blockIdx.x * blockDim.x + threadIdx.x;
    const float* srcp;
    __half* dstp;
    if (i < n8feat) {
        srcp = feat + (size_t)i * 8;
        dstp = g_feat_h + (size_t)i * 8;
    } else {
        int j = i - n8feat;
        if (j >= HF * IN_FEATS / 8) return;
        srcp = W + (size_t)j * 8;
        dstp = g_w_h + (size_t)j * 8;
    }
    const float4* p = (const float4*)srcp;
    float4 a = p[0], b = p[1];
    __half2 h0 = __floats2half2_rn(a.x, a.y);
    __half2 h1 = __floats2half2_rn(a.z, a.w);
    __half2 h2 = __floats2half2_rn(b.x, b.y);
    __half2 h3 = __floats2half2_rn(b.z, b.w);
    uint4 pk;
    pk.x = *(unsigned*)&h0; pk.y = *(unsigned*)&h1;
    pk.z = *(unsigned*)&h2; pk.w = *(unsigned*)&h3;
    *(uint4*)dstp = pk;
}

// ---------------- 1) HMMA GEMM (BM=128, BN=128, BK=32), 2 blocks/SM ----------------
// Epilogue staged in TWO WAVES of 4 warps -> dynamic smem 36 KB -> occupancy 2x.
#define GEMM_SMEM_BYTES 36864   // max(2*128*40*2 = 20480 staging, 4*32*72*4 = 36864 epilogue)

__global__ void __launch_bounds__(256, 2) gemm_wmma_kernel(const float* __restrict__ attn_l,
                                                           const float* __restrict__ attn_r,
                                                           int M) {
    extern __shared__ char dynsmem[];
    __half* As = (__half*)dynsmem;            // [128][40]
    __half* Bs = As + 128 * 40;               // [128][40]
    float*  epi = (float*)dynsmem;            // reuse: [4][32][72]
    __shared__ float al_s[128], ar_s[128];

    const int m0 = blockIdx.x * 128;
    const int n0 = blockIdx.y * 128;
    const int tid = threadIdx.x;
    const int warp = tid >> 5;
    const int lane = tid & 31;
    const int wy = warp >> 1;   // 0..3 (m)
    const int wx = warp & 1;    // 0..1 (n)

    if (tid < 128) {
        al_s[tid] = attn_l[n0 + tid];
        ar_s[tid] = attn_r[n0 + tid];
    }

    const int idx0 = tid, idx1 = tid + 256;
    const int r0i = idx0 >> 2, q0 = idx0 & 3;
    const int r1i = idx1 >> 2, q1 = idx1 & 3;

    uint4 a0, a1, b0, b1;
    const uint4 zero4 = make_uint4(0, 0, 0, 0);

    {
        int gr0 = m0 + r0i, gr1 = m0 + r1i;
        a0 = (gr0 < M) ? *(const uint4*)(g_feat_h + (size_t)gr0 * IN_FEATS + q0 * 8) : zero4;
        a1 = (gr1 < M) ? *(const uint4*)(g_feat_h + (size_t)gr1 * IN_FEATS + q1 * 8) : zero4;
        b0 = *(const uint4*)(g_w_h + (size_t)(n0 + r0i) * IN_FEATS + q0 * 8);
        b1 = *(const uint4*)(g_w_h + (size_t)(n0 + r1i) * IN_FEATS + q1 * 8);
    }
    *(uint4*)(As + r0i * 40 + q0 * 8) = a0;
    *(uint4*)(As + r1i * 40 + q1 * 8) = a1;
    *(uint4*)(Bs + r0i * 40 + q0 * 8) = b0;
    *(uint4*)(Bs + r1i * 40 + q1 * 8) = b1;
    __syncthreads();

    wmma::fragment<wmma::accumulator, 16, 16, 16, float> acc[2][4];
#pragma unroll
    for (int i = 0; i < 2; i++)
#pragma unroll
        for (int j = 0; j < 4; j++) wmma::fill_fragment(acc[i][j], 0.0f);

#pragma unroll 1
    for (int k0 = 0; k0 < IN_FEATS; k0 += 32) {
        const bool more = (k0 + 32 < IN_FEATS);
        if (more) {
            int kn = k0 + 32;
            int gr0 = m0 + r0i, gr1 = m0 + r1i;
            a0 = (gr0 < M) ? *(const uint4*)(g_feat_h + (size_t)gr0 * IN_FEATS + kn + q0 * 8) : zero4;
            a1 = (gr1 < M) ? *(const uint4*)(g_feat_h + (size_t)gr1 * IN_FEATS + kn + q1 * 8) : zero4;
            b0 = *(const uint4*)(g_w_h + (size_t)(n0 + r0i) * IN_FEATS + kn + q0 * 8);
            b1 = *(const uint4*)(g_w_h + (size_t)(n0 + r1i) * IN_FEATS + kn + q1 * 8);
        }

#pragma unroll
        for (int ks = 0; ks < 32; ks += 16) {
            wmma::fragment<wmma::matrix_a, 16, 16, 16, __half, wmma::row_major> fa[2];
            wmma::fragment<wmma::matrix_b, 16, 16, 16, __half, wmma::col_major> fb[4];
#pragma unroll
            for (int i = 0; i < 2; i++)
                wmma::load_matrix_sync(fa[i], As + (wy * 32 + i * 16) * 40 + ks, 40);
#pragma unroll
            for (int j = 0; j < 4; j++)
                wmma::load_matrix_sync(fb[j], Bs + (wx * 64 + j * 16) * 40 + ks, 40);
#pragma unroll
            for (int i = 0; i < 2; i++)
#pragma unroll
                for (int j = 0; j < 4; j++)
                    wmma::mma_sync(acc[i][j], fa[i], fb[j], acc[i][j]);
        }
        __syncthreads();

        if (more) {
            *(uint4*)(As + r0i * 40 + q0 * 8) = a0;
            *(uint4*)(As + r1i * 40 + q1 * 8) = a1;
            *(uint4*)(Bs + r0i * 40 + q0 * 8) = b0;
            *(uint4*)(Bs + r1i * 40 + q1 * 8) = b1;
            __syncthreads();
        }
    }

    // all warps done reading As/Bs before the epilogue aliases that smem
    __syncthreads();

    // ---- two-wave epilogue: 4 warps stage at a time (halves smem -> 2 blocks/SM) ----
#pragma unroll
    for (int wave = 0; wave < 2; wave++) {
        if ((warp >> 2) == wave) {
            float* ws = epi + (warp & 3) * 32 * 72;
#pragma unroll
            for (int i = 0; i < 2; i++)
#pragma unroll
                for (int j = 0; j < 4; j++)
                    wmma::store_matrix_sync(ws + i * 16 * 72 + j * 16, acc[i][j], 72,
                                            wmma::mem_row_major);
            __syncwarp();

            const int grow = m0 + wy * 32 + lane;
            const float* al = al_s + wx * 64;
            const float* ar = ar_s + wx * 64;
            const float* hr = ws + lane * 72;

            float el0 = 0.f, er0 = 0.f, el1 = 0.f, er1 = 0.f;
#pragma unroll
            for (int c = 0; c < 32; c++) {
                float v = hr[c];
                el0 = fmaf(v, al[c], el0);
                er0 = fmaf(v, ar[c], er0);
            }
#pragma unroll
            for (int c = 32; c < 64; c++) {
                float v = hr[c];
                el1 = fmaf(v, al[c], el1);
                er1 = fmaf(v, ar[c], er1);
            }

            if (grow < M) {
                __half* hrow = g_hh + (size_t)grow * HF + n0 + wx * 64;
#pragma unroll
                for (int c8 = 0; c8 < 8; c8++) {
                    __half2 h0 = __floats2half2_rn(hr[c8 * 8 + 0], hr[c8 * 8 + 1]);
                    __half2 h1 = __floats2half2_rn(hr[c8 * 8 + 2], hr[c8 * 8 + 3]);
                    __half2 h2 = __floats2half2_rn(hr[c8 * 8 + 4], hr[c8 * 8 + 5]);
                    __half2 h3 = __floats2half2_rn(hr[c8 * 8 + 6], hr[c8 * 8 + 7]);
                    uint4 pk;
                    pk.x = *(unsigned*)&h0; pk.y = *(unsigned*)&h1;
                    pk.z = *(unsigned*)&h2; pk.w = *(unsigned*)&h3;
                    *(uint4*)(hrow + c8 * 8) = pk;
                }
                int hb = (n0 + wx * 64) >> 5;
                g_el[(size_t)grow * HEADS + hb] = el0;
                g_el[(size_t)grow * HEADS + hb + 1] = el1;
                g_er[(size_t)grow * HEADS + hb] = er0;
                g_er[(size_t)grow * HEADS + hb + 1] = er1;
            }
        }
        __syncthreads();
    }
}

// ---------------- 2) CSR build (rank-based, atomic-free scatter) ----------------
__global__ void hist_kernel(const int* __restrict__ dst, int E) {
    int i = (blockIdx.x * blockDim.x + threadIdx.x) * 4;
    if (i + 4 <= E) {
        int4 d = __ldcs((const int4*)(dst + i));
        int4 r;
        r.x = atomicAdd(&g_cnt[d.x], 1);
        r.y = atomicAdd(&g_cnt[d.y], 1);
        r.z = atomicAdd(&g_cnt[d.z], 1);
        r.w = atomicAdd(&g_cnt[d.w], 1);
        *(int4*)(g_rank + i) = r;
    } else {
        for (int k = i; k < E; k++) g_rank[k] = atomicAdd(&g_cnt[dst[k]], 1);
    }
}

__global__ void __launch_bounds__(512) partial_sum_kernel(int N) {
    __shared__ int wsum[16];
    int b = blockIdx.x, tid = threadIdx.x;
    int base = b * SCAN_CHUNK + tid * 8;
    int s = 0;
    if (base + 8 <= N) {
        int4 a = *(const int4*)(g_cnt + base);
        int4 c = *(const int4*)(g_cnt + base + 4);
        s = a.x + a.y + a.z + a.w + c.x + c.y + c.z + c.w;
    } else {
#pragma unroll
        for (int k = 0; k < 8; k++) { int i = base + k; if (i < N) s += g_cnt[i]; }
    }
    int lane = tid & 31, wid = tid >> 5;
#pragma unroll
    for (int d = 16; d > 0; d >>= 1) s += __shfl_xor_sync(FULL, s, d);
    if (lane == 0) wsum[wid] = s;
    __syncthreads();
    if (wid == 0) {
        int w = (lane < 16) ? wsum[lane] : 0;
#pragma unroll
        for (int d = 16; d > 0; d >>= 1) w += __shfl_xor_sync(FULL, w, d);
        if (lane == 0) g_blksum[b] = w;
    }
}

__global__ void scan_blk_kernel(int nb, int E, int N) {
    int lane = threadIdx.x;
    int v = (lane < nb) ? g_blksum[lane] : 0;
    int x = v;
#pragma unroll
    for (int d = 1; d < 32; d <<= 1) {
        int y = __shfl_up_sync(FULL, x, d);
        if (lane >= d) x += y;
    }
    if (lane < nb) g_blkoff[lane] = x - v;
    if (lane == 0) g_row_off[N] = E;
}

__global__ void __launch_bounds__(512) scan_final_kernel(int N) {
    __shared__ int wsum[16];
    __shared__ int blk_base;
    int b = blockIdx.x, tid = threadIdx.x;
    int lane = tid & 31, wid = tid >> 5;
    if (tid == 0) blk_base = g_blkoff[b];

    int base = b * SCAN_CHUNK + tid * 8;
    int v[8];
#pragma unroll
    for (int k = 0; k < 8; k++) { int i = base + k; v[k] = (i < N) ? g_cnt[i] : 0; }
    int tot = 0;
#pragma unroll
    for (int k = 0; k < 8; k++) { int t = v[k]; v[k] = tot; tot += t; }

    int x = tot;
#pragma unroll
    for (int d = 1; d < 32; d <<= 1) {
        int y = __shfl_up_sync(FULL, x, d);
        if (lane >= d) x += y;
    }
    if (lane == 31) wsum[wid] = x;
    __syncthreads();
    if (wid == 0) {
        int w = (lane < 16) ? wsum[lane] : 0;
#pragma unroll
        for (int d = 1; d < 32; d <<= 1) {
            int y = __shfl_up_sync(FULL, w, d);
            if (lane >= d) w += y;
        }
        if (lane < 16) wsum[lane] = w;
    }
    __syncthreads();
    int toff = x - tot + ((wid > 0) ? wsum[wid - 1] : 0) + blk_base;
#pragma unroll
    for (int k = 0; k < 8; k++) {
        int i = base + k;
        if (i < N) g_row_off[i] = toff + v[k];
    }
}

__global__ void scatter_kernel(const int* __restrict__ src,
                               const int* __restrict__ dst, int E, int N) {
    int t = blockIdx.x * blockDim.x + threadIdx.x;
    if (t < N) g_cnt[t] = 0;
    int i = t * 4;
    if (i + 4 <= E) {
        int4 s = __ldcs((const int4*)(src + i));
        int4 d = __ldcs((const int4*)(dst + i));
        int4 r = *(const int4*)(g_rank + i);
        g_csr_src[g_row_off[d.x] + r.x] = s.x;
        g_csr_src[g_row_off[d.y] + r.y] = s.y;
        g_csr_src[g_row_off[d.z] + r.z] = s.z;
        g_csr_src[g_row_off[d.w] + r.w] = s.w;
    } else {
        for (int k = i; k < E; k++)
            g_csr_src[g_row_off[dst[k]] + g_rank[k]] = src[k];
    }
}

// ---------------- 3) single-pass pipelined softmax + fp16 aggregation ----------------
__global__ void __launch_bounds__(256) gat_agg_kernel(const float* __restrict__ bias,
                                                      float* __restrict__ out, int N) {
    int gwarp = (blockIdx.x * blockDim.x + threadIdx.x) >> 5;
    int lane = threadIdx.x & 31;
    if (gwarp >= N) return;

    const int n = gwarp;
    const int base = g_row_off[n];
    const int deg = g_row_off[n + 1] - base;

    float* orow = out + (size_t)n * HF;
    const float4* b4 = (const float4*)bias;
    float4 bv0 = b4[lane * 2], bv1 = b4[lane * 2 + 1];

    if (deg == 0) {
        __stcs((float4*)orow + lane * 2, bv0);
        __stcs((float4*)orow + lane * 2 + 1, bv1);
        return;
    }

    const int lane3 = lane & 3;
    const int hh = lane & 7;
    const int q = lane >> 3;
    const int gh = lane >> 2;
    const float er_h = __ldg(g_er + (size_t)n * HEADS + hh);

    float acc[8];
#pragma unroll
    for (int j = 0; j < 8; j++) acc[j] = 0.f;
    float smp = 0.f;

    int sj_c;
    {
        int i4 = lane3;
        sj_c = __ldcs(g_csr_src + base + ((i4 < deg) ? i4 : (deg - 1)));
    }
    float c_c;
    {
        int sq = __shfl_sync(FULL, sj_c, q);
        float e = __ldg(g_el + (size_t)sq * HEADS + hh) + er_h;
        e = (e > 0.f) ? e : NEG_SLOPE * e;
        c_c = (q < deg) ? __expf(e) : 0.f;
    }

    for (int j = 0; j < deg; j += 4) {
        const int jn = j + 4;
        const bool more = jn < deg;

        int sj_n = 0;
        if (more) {
            int i4 = jn + lane3;
            sj_n = __ldcs(g_csr_src + base + ((i4 < deg) ? i4 : (deg - 1)));
        }

        int s0 = __shfl_sync(FULL, sj_c, 0);
        int s1 = __shfl_sync(FULL, sj_c, 1);
        int s2 = __shfl_sync(FULL, sj_c, 2);
        int s3 = __shfl_sync(FULL, sj_c, 3);
        float c0 = __shfl_sync(FULL, c_c, gh);
        float c1 = __shfl_sync(FULL, c_c, 8 + gh);
        float c2 = __shfl_sync(FULL, c_c, 16 + gh);
        float c3 = __shfl_sync(FULL, c_c, 24 + gh);
        smp += c_c;

        uint4 w0 = *((const uint4*)(g_hh + (size_t)s0 * HF) + lane);
        uint4 w1 = *((const uint4*)(g_hh + (size_t)s1 * HF) + lane);
        uint4 w2 = *((const uint4*)(g_hh + (size_t)s2 * HF) + lane);
        uint4 w3 = *((const uint4*)(g_hh + (size_t)s3 * HF) + lane);

        float c_n = 0.f;
        if (more) {
            int sqn = __shfl_sync(FULL, sj_n, q);
            float en = __ldg(g_el + (size_t)sqn * HEADS + hh) + er_h;
            en = (en > 0.f) ? en : NEG_SLOPE * en;
            c_n = ((jn + q) < deg) ? __expf(en) : 0.f;
        }

#define AGG_EDGE(W, C)                                                        \
        {                                                                     \
            float2 f0 = __half22float2(*(const __half2*)&(W).x);              \
            float2 f1 = __half22float2(*(const __half2*)&(W).y);              \
            float2 f2 = __half22float2(*(const __half2*)&(W).z);              \
            float2 f3 = __half22float2(*(const __half2*)&(W).w);              \
            acc[0] = fmaf(f0.x, (C), acc[0]); acc[1] = fmaf(f0.y, (C), acc[1]); \
            acc[2] = fmaf(f1.x, (C), acc[2]); acc[3] = fmaf(f1.y, (C), acc[3]); \
            acc[4] = fmaf(f2.x, (C), acc[4]); acc[5] = fmaf(f2.y, (C), acc[5]); \
            acc[6] = fmaf(f3.x, (C), acc[6]); acc[7] = fmaf(f3.y, (C), acc[7]); \
        }
        AGG_EDGE(w0, c0) AGG_EDGE(w1, c1) AGG_EDGE(w2, c2) AGG_EDGE(w3, c3)
#undef AGG_EDGE

        sj_c = sj_n;
        c_c = c_n;
    }

    smp += __shfl_xor_sync(FULL, smp, 8);
    smp += __shfl_xor_sync(FULL, smp, 16);
    float inv = 1.0f / smp;
    float cinv = __shfl_sync(FULL, inv, gh);

    __stcs((float4*)orow + lane * 2,
           make_float4(fmaf(acc[0], cinv, bv0.x), fmaf(acc[1], cinv, bv0.y),
                       fmaf(acc[2], cinv, bv0.z), fmaf(acc[3], cinv, bv0.w)));
    __stcs((float4*)orow + lane * 2 + 1,
           make_float4(fmaf(acc[4], cinv, bv1.x), fmaf(acc[5], cinv, bv1.y),
                       fmaf(acc[6], cinv, bv1.z), fmaf(acc[7], cinv, bv1.w)));
}

// ---------------- launch (fork-join; gemm is submission index 3 for ncu capture) ----------------
static cudaStream_t get_side_stream() {
    static cudaStream_t s = [] {
        cudaStream_t t;
        cudaStreamCreateWithFlags(&t, cudaStreamNonBlocking);
        return t;
    }();
    return s;
}
static cudaEvent_t get_ev(int which) {
    static cudaEvent_t e0 = [] {
        cudaEvent_t e; cudaEventCreateWithFlags(&e, cudaEventDisableTiming); return e;
    }();
    static cudaEvent_t e1 = [] {
        cudaEvent_t e; cudaEventCreateWithFlags(&e, cudaEventDisableTiming); return e;
    }();
    return which ? e1 : e0;
}

extern "C" void kernel_launch(void* const* d_in, const int* in_sizes, int n_in,
                              void* d_out, int out_size) {
    const float* feat   = (const float*)d_in[0];
    const int*   src    = (const int*)d_in[1];
    const int*   dst    = (const int*)d_in[2];
    const float* fc_w   = (const float*)d_in[3];
    const float* attn_l = (const float*)d_in[4];
    const float* attn_r = (const float*)d_in[5];
    const float* bias   = (const float*)d_in[6];
    float* out = (float*)d_out;

    const int M = in_sizes[0] / IN_FEATS;
    const int E = in_sizes[1];

    cudaFuncSetAttribute(gemm_wmma_kernel,
                         cudaFuncAttributeMaxDynamicSharedMemorySize, GEMM_SMEM_BYTES);

    cudaStream_t sB = get_side_stream();
    cudaEvent_t evF = get_ev(0), evJ = get_ev(1);

    cudaEventRecord(evF, 0);
    cudaStreamWaitEvent(sB, evF, 0);

    // [0] main: fused fp32->fp16 convert (feat + weights)
    int n8feat = M * (IN_FEATS / 8);
    int n8all = n8feat + HF * IN_FEATS / 8;
    cvt_all_kernel<<<(n8all + 255) / 256, 256>>>(feat, fc_w, n8feat);
    // [1] side: histogram + per-edge rank
    hist_kernel<<<(E / 4 + 255) / 256, 256, 0, sB>>>(dst, E);
    // [2] side: partial sums
    int nb = (M + SCAN_CHUNK - 1) / SCAN_CHUNK;
    partial_sum_kernel<<<nb, 512, 0, sB>>>(M);
    // [3] main: tensor-core GEMM + fused el/er  (ncu capture target)
    dim3 ggrid((M + 127) / 128, HF / 128);
    gemm_wmma_kernel<<<ggrid, 256, GEMM_SMEM_BYTES>>>(attn_l, attn_r, M);
    // [4..6] side: scan + atomic-free scatter (also re-zeroes g_cnt)
    scan_blk_kernel<<<1, 32, 0, sB>>>(nb, E, M);
    scan_final_kernel<<<nb, 512, 0, sB>>>(M);
    scatter_kernel<<<(E / 4 + 255) / 256, 256, 0, sB>>>(src, dst, E, M);

    cudaEventRecord(evJ, sB);
    cudaStreamWaitEvent(0, evJ, 0);

    // [7] main: fused softmax + aggregation
    int warp_blocks = (M * 32 + 255) / 256;
    gat_agg_kernel<<<warp_blocks, 256>>>(bias, out, M);
}

// round 16
// speedup vs baseline: 1.0617x; 1.0191x over previous
#include <cuda_runtime.h>
#include <cuda_fp16.h>
#include <mma.h>
#include <math.h>
#include <cstdint>

using namespace nvcuda;

#define HEADS 8
#define OUTF 32
#define HF 256
#define IN_FEATS 256
#define NEG_SLOPE 0.2f
#define SCAN_CHUNK 4096
#define N_NODES_MAX 100000
#define N_EDGES_MAX 3200000
#define FULL 0xffffffffu

// ---------------- device scratch ----------------
__device__ __align__(16) __half g_hh[(size_t)N_NODES_MAX * HF];      // projected features, fp16
__device__ __align__(16) __half g_feat_h[(size_t)N_NODES_MAX * IN_FEATS]; // feat fp16
__device__ __align__(16) __half g_w_h[HF * IN_FEATS];                // weights fp16
__device__ float g_el[N_NODES_MAX * HEADS];
__device__ float g_er[N_NODES_MAX * HEADS];
__device__ int   g_cnt[N_NODES_MAX];          // zero at load; re-zeroed by scatter each call
__device__ int   g_row_off[N_NODES_MAX + 1];
__device__ int   g_rank[N_EDGES_MAX];         // edge rank within its dst segment
__device__ int   g_csr_src[N_EDGES_MAX];
__device__ int   g_blksum[64];
__device__ int   g_blkoff[64];

// ---------------- cp.async helpers ----------------
__device__ __forceinline__ void cp_async16(unsigned int smem_addr, const void* gptr, bool valid) {
    int sz = valid ? 16 : 0;
    asm volatile("cp.async.cg.shared.global [%0], [%1], 16, %2;"
                 :: "r"(smem_addr), "l"(gptr), "r"(sz));
}
__device__ __forceinline__ void cp_async_commit() {
    asm volatile("cp.async.commit_group;");
}

// ---------------- fused fp32 -> fp16 converter (feat then weights) ----------------
__global__ void cvt_all_kernel(const float* __restrict__ feat,
                               const float* __restrict__ W, int n8feat) {
    int i = blockIdx.x * blockDim.x + threadIdx.x;
    const float* srcp;
    __half* dstp;
    if (i < n8feat) {
        srcp = feat + (size_t)i * 8;
        dstp = g_feat_h + (size_t)i * 8;
    } else {
        int j = i - n8feat;
        if (j >= HF * IN_FEATS / 8) return;
        srcp = W + (size_t)j * 8;
        dstp = g_w_h + (size_t)j * 8;
    }
    const float4* p = (const float4*)srcp;
    float4 a = p[0], b = p[1];
    __half2 h0 = __floats2half2_rn(a.x, a.y);
    __half2 h1 = __floats2half2_rn(a.z, a.w);
    __half2 h2 = __floats2half2_rn(b.x, b.y);
    __half2 h3 = __floats2half2_rn(b.z, b.w);
    uint4 pk;
    pk.x = *(unsigned*)&h0; pk.y = *(unsigned*)&h1;
    pk.z = *(unsigned*)&h2; pk.w = *(unsigned*)&h3;
    *(uint4*)dstp = pk;
}

// ---------------- 1) HMMA GEMM (BM=128, BN=128, BK=32), cp.async double-buffered ----------------
// Two smem tile buffers (40 KB) replace register prefetch; epilogue (36 KB) aliases them.
#define GEMM_SMEM_BYTES 40960

__global__ void __launch_bounds__(256, 2) gemm_wmma_kernel(const float* __restrict__ attn_l,
                                                           const float* __restrict__ attn_r,
                                                           int M) {
    extern __shared__ char dynsmem[];
    __half* As = (__half*)dynsmem;            // [2][128][40]
    __half* Bs = As + 2 * 128 * 40;           // [2][128][40]
    float*  epi = (float*)dynsmem;            // reuse: [4][32][72]
    __shared__ float al_s[128], ar_s[128];

    const int m0 = blockIdx.x * 128;
    const int n0 = blockIdx.y * 128;
    const int tid = threadIdx.x;
    const int warp = tid >> 5;
    const int lane = tid & 31;
    const int wy = warp >> 1;   // 0..3 (m)
    const int wx = warp & 1;    // 0..1 (n)

    if (tid < 128) {
        al_s[tid] = attn_l[n0 + tid];
        ar_s[tid] = attn_r[n0 + tid];
    }

    // loader mapping: 512 chunks per tile per matrix; 2 per thread each
    const int idx0 = tid, idx1 = tid + 256;
    const int r0i = idx0 >> 2, q0 = idx0 & 3;
    const int r1i = idx1 >> 2, q1 = idx1 & 3;
    const bool v0 = (m0 + r0i) < M;
    const bool v1 = (m0 + r1i) < M;

    const unsigned int asm0 = (unsigned int)__cvta_generic_to_shared(As + r0i * 40 + q0 * 8);
    const unsigned int asm1 = (unsigned int)__cvta_generic_to_shared(As + r1i * 40 + q1 * 8);
    const unsigned int bsm0 = (unsigned int)__cvta_generic_to_shared(Bs + r0i * 40 + q0 * 8);
    const unsigned int bsm1 = (unsigned int)__cvta_generic_to_shared(Bs + r1i * 40 + q1 * 8);
    const unsigned int ABUF = 128 * 40 * 2;  // bytes per buffer
    const __half* ga0 = g_feat_h + (size_t)(m0 + r0i) * IN_FEATS + q0 * 8;
    const __half* ga1 = g_feat_h + (size_t)(m0 + r1i) * IN_FEATS + q1 * 8;
    const __half* gb0 = g_w_h + (size_t)(n0 + r0i) * IN_FEATS + q0 * 8;
    const __half* gb1 = g_w_h + (size_t)(n0 + r1i) * IN_FEATS + q1 * 8;

    auto issue_tile = [&](int buf, int k0) {
        cp_async16(asm0 + buf * ABUF, ga0 + k0, v0);
        cp_async16(asm1 + buf * ABUF, ga1 + k0, v1);
        cp_async16(bsm0 + buf * ABUF, gb0 + k0, true);
        cp_async16(bsm1 + buf * ABUF, gb1 + k0, true);
        cp_async_commit();
    };

    issue_tile(0, 0);

    wmma::fragment<wmma::accumulator, 16, 16, 16, float> acc[2][4];
#pragma unroll
    for (int i = 0; i < 2; i++)
#pragma unroll
        for (int j = 0; j < 4; j++) wmma::fill_fragment(acc[i][j], 0.0f);

    int p = 0;
#pragma unroll 1
    for (int k0 = 0; k0 < IN_FEATS; k0 += 32) {
        const bool more = (k0 + 32 < IN_FEATS);
        if (more) issue_tile(p ^ 1, k0 + 32);

        if (more) asm volatile("cp.async.wait_group 1;");
        else      asm volatile("cp.async.wait_group 0;");
        __syncthreads();

        const __half* Ab = As + p * 128 * 40;
        const __half* Bb = Bs + p * 128 * 40;
#pragma unroll
        for (int ks = 0; ks < 32; ks += 16) {
            wmma::fragment<wmma::matrix_a, 16, 16, 16, __half, wmma::row_major> fa[2];
            wmma::fragment<wmma::matrix_b, 16, 16, 16, __half, wmma::col_major> fb[4];
#pragma unroll
            for (int i = 0; i < 2; i++)
                wmma::load_matrix_sync(fa[i], Ab + (wy * 32 + i * 16) * 40 + ks, 40);
#pragma unroll
            for (int j = 0; j < 4; j++)
                wmma::load_matrix_sync(fb[j], Bb + (wx * 64 + j * 16) * 40 + ks, 40);
#pragma unroll
            for (int i = 0; i < 2; i++)
#pragma unroll
                for (int j = 0; j < 4; j++)
                    wmma::mma_sync(acc[i][j], fa[i], fb[j], acc[i][j]);
        }
        __syncthreads();   // all warps done with buf p before it is overwritten
        p ^= 1;
    }

    // ---- two-wave epilogue (aliases tile smem; 4 warps stage at a time) ----
#pragma unroll
    for (int wave = 0; wave < 2; wave++) {
        if ((warp >> 2) == wave) {
            float* ws = epi + (warp & 3) * 32 * 72;
#pragma unroll
            for (int i = 0; i < 2; i++)
#pragma unroll
                for (int j = 0; j < 4; j++)
                    wmma::store_matrix_sync(ws + i * 16 * 72 + j * 16, acc[i][j], 72,
                                            wmma::mem_row_major);
            __syncwarp();

            const int grow = m0 + wy * 32 + lane;
            const float* al = al_s + wx * 64;
            const float* ar = ar_s + wx * 64;
            const float* hr = ws + lane * 72;

            float el0 = 0.f, er0 = 0.f, el1 = 0.f, er1 = 0.f;
#pragma unroll
            for (int c = 0; c < 32; c++) {
                float v = hr[c];
                el0 = fmaf(v, al[c], el0);
                er0 = fmaf(v, ar[c], er0);
            }
#pragma unroll
            for (int c = 32; c < 64; c++) {
                float v = hr[c];
                el1 = fmaf(v, al[c], el1);
                er1 = fmaf(v, ar[c], er1);
            }

            if (grow < M) {
                __half* hrow = g_hh + (size_t)grow * HF + n0 + wx * 64;
#pragma unroll
                for (int c8 = 0; c8 < 8; c8++) {
                    __half2 h0 = __floats2half2_rn(hr[c8 * 8 + 0], hr[c8 * 8 + 1]);
                    __half2 h1 = __floats2half2_rn(hr[c8 * 8 + 2], hr[c8 * 8 + 3]);
                    __half2 h2 = __floats2half2_rn(hr[c8 * 8 + 4], hr[c8 * 8 + 5]);
                    __half2 h3 = __floats2half2_rn(hr[c8 * 8 + 6], hr[c8 * 8 + 7]);
                    uint4 pk;
                    pk.x = *(unsigned*)&h0; pk.y = *(unsigned*)&h1;
                    pk.z = *(unsigned*)&h2; pk.w = *(unsigned*)&h3;
                    *(uint4*)(hrow + c8 * 8) = pk;
                }
                int hb = (n0 + wx * 64) >> 5;
                g_el[(size_t)grow * HEADS + hb] = el0;
                g_el[(size_t)grow * HEADS + hb + 1] = el1;
                g_er[(size_t)grow * HEADS + hb] = er0;
                g_er[(size_t)grow * HEADS + hb + 1] = er1;
            }
        }
        __syncthreads();
    }
}

// ---------------- 2) CSR build (rank-based, atomic-free scatter) ----------------
__global__ void hist_kernel(const int* __restrict__ dst, int E) {
    int i = (blockIdx.x * blockDim.x + threadIdx.x) * 4;
    if (i + 4 <= E) {
        int4 d = __ldcs((const int4*)(dst + i));
        int4 r;
        r.x = atomicAdd(&g_cnt[d.x], 1);
        r.y = atomicAdd(&g_cnt[d.y], 1);
        r.z = atomicAdd(&g_cnt[d.z], 1);
        r.w = atomicAdd(&g_cnt[d.w], 1);
        *(int4*)(g_rank + i) = r;
    } else {
        for (int k = i; k < E; k++) g_rank[k] = atomicAdd(&g_cnt[dst[k]], 1);
    }
}

__global__ void __launch_bounds__(512) partial_sum_kernel(int N) {
    __shared__ int wsum[16];
    int b = blockIdx.x, tid = threadIdx.x;
    int base = b * SCAN_CHUNK + tid * 8;
    int s = 0;
    if (base + 8 <= N) {
        int4 a = *(const int4*)(g_cnt + base);
        int4 c = *(const int4*)(g_cnt + base + 4);
        s = a.x + a.y + a.z + a.w + c.x + c.y + c.z + c.w;
    } else {
#pragma unroll
        for (int k = 0; k < 8; k++) { int i = base + k; if (i < N) s += g_cnt[i]; }
    }
    int lane = tid & 31, wid = tid >> 5;
#pragma unroll
    for (int d = 16; d > 0; d >>= 1) s += __shfl_xor_sync(FULL, s, d);
    if (lane == 0) wsum[wid] = s;
    __syncthreads();
    if (wid == 0) {
        int w = (lane < 16) ? wsum[lane] : 0;
#pragma unroll
        for (int d = 16; d > 0; d >>= 1) w += __shfl_xor_sync(FULL, w, d);
        if (lane == 0) g_blksum[b] = w;
    }
}

__global__ void scan_blk_kernel(int nb, int E, int N) {
    int lane = threadIdx.x;
    int v = (lane < nb) ? g_blksum[lane] : 0;
    int x = v;
#pragma unroll
    for (int d = 1; d < 32; d <<= 1) {
        int y = __shfl_up_sync(FULL, x, d);
        if (lane >= d) x += y;
    }
    if (lane < nb) g_blkoff[lane] = x - v;
    if (lane == 0) g_row_off[N] = E;
}

__global__ void __launch_bounds__(512) scan_final_kernel(int N) {
    __shared__ int wsum[16];
    __shared__ int blk_base;
    int b = blockIdx.x, tid = threadIdx.x;
    int lane = tid & 31, wid = tid >> 5;
    if (tid == 0) blk_base = g_blkoff[b];

    int base = b * SCAN_CHUNK + tid * 8;
    int v[8];
#pragma unroll
    for (int k = 0; k < 8; k++) { int i = base + k; v[k] = (i < N) ? g_cnt[i] : 0; }
    int tot = 0;
#pragma unroll
    for (int k = 0; k < 8; k++) { int t = v[k]; v[k] = tot; tot += t; }

    int x = tot;
#pragma unroll
    for (int d = 1; d < 32; d <<= 1) {
        int y = __shfl_up_sync(FULL, x, d);
        if (lane >= d) x += y;
    }
    if (lane == 31) wsum[wid] = x;
    __syncthreads();
    if (wid == 0) {
        int w = (lane < 16) ? wsum[lane] : 0;
#pragma unroll
        for (int d = 1; d < 32; d <<= 1) {
            int y = __shfl_up_sync(FULL, w, d);
            if (lane >= d) w += y;
        }
        if (lane < 16) wsum[lane] = w;
    }
    __syncthreads();
    int toff = x - tot + ((wid > 0) ? wsum[wid - 1] : 0) + blk_base;
#pragma unroll
    for (int k = 0; k < 8; k++) {
        int i = base + k;
        if (i < N) g_row_off[i] = toff + v[k];
    }
}

__global__ void scatter_kernel(const int* __restrict__ src,
                               const int* __restrict__ dst, int E, int N) {
    int t = blockIdx.x * blockDim.x + threadIdx.x;
    if (t < N) g_cnt[t] = 0;
    int i = t * 4;
    if (i + 4 <= E) {
        int4 s = __ldcs((const int4*)(src + i));
        int4 d = __ldcs((const int4*)(dst + i));
        int4 r = *(const int4*)(g_rank + i);
        g_csr_src[g_row_off[d.x] + r.x] = s.x;
        g_csr_src[g_row_off[d.y] + r.y] = s.y;
        g_csr_src[g_row_off[d.z] + r.z] = s.z;
        g_csr_src[g_row_off[d.w] + r.w] = s.w;
    } else {
        for (int k = i; k < E; k++)
            g_csr_src[g_row_off[dst[k]] + g_rank[k]] = src[k];
    }
}

// ---------------- 3) single-pass pipelined softmax + fp16 aggregation ----------------
__global__ void __launch_bounds__(256) gat_agg_kernel(const float* __restrict__ bias,
                                                      float* __restrict__ out, int N) {
    int gwarp = (blockIdx.x * blockDim.x + threadIdx.x) >> 5;
    int lane = threadIdx.x & 31;
    if (gwarp >= N) return;

    const int n = gwarp;
    const int base = g_row_off[n];
    const int deg = g_row_off[n + 1] - base;

    float* orow = out + (size_t)n * HF;
    const float4* b4 = (const float4*)bias;
    float4 bv0 = b4[lane * 2], bv1 = b4[lane * 2 + 1];

    if (deg == 0) {
        __stcs((float4*)orow + lane * 2, bv0);
        __stcs((float4*)orow + lane * 2 + 1, bv1);
        return;
    }

    const int lane3 = lane & 3;
    const int hh = lane & 7;
    const int q = lane >> 3;
    const int gh = lane >> 2;
    const float er_h = __ldg(g_er + (size_t)n * HEADS + hh);

    float acc[8];
#pragma unroll
    for (int j = 0; j < 8; j++) acc[j] = 0.f;
    float smp = 0.f;

    int sj_c;
    {
        int i4 = lane3;
        sj_c = __ldcs(g_csr_src + base + ((i4 < deg) ? i4 : (deg - 1)));
    }
    float c_c;
    {
        int sq = __shfl_sync(FULL, sj_c, q);
        float e = __ldg(g_el + (size_t)sq * HEADS + hh) + er_h;
        e = (e > 0.f) ? e : NEG_SLOPE * e;
        c_c = (q < deg) ? __expf(e) : 0.f;
    }

    for (int j = 0; j < deg; j += 4) {
        const int jn = j + 4;
        const bool more = jn < deg;

        int sj_n = 0;
        if (more) {
            int i4 = jn + lane3;
            sj_n = __ldcs(g_csr_src + base + ((i4 < deg) ? i4 : (deg - 1)));
        }

        int s0 = __shfl_sync(FULL, sj_c, 0);
        int s1 = __shfl_sync(FULL, sj_c, 1);
        int s2 = __shfl_sync(FULL, sj_c, 2);
        int s3 = __shfl_sync(FULL, sj_c, 3);
        float c0 = __shfl_sync(FULL, c_c, gh);
        float c1 = __shfl_sync(FULL, c_c, 8 + gh);
        float c2 = __shfl_sync(FULL, c_c, 16 + gh);
        float c3 = __shfl_sync(FULL, c_c, 24 + gh);
        smp += c_c;

        uint4 w0 = *((const uint4*)(g_hh + (size_t)s0 * HF) + lane);
        uint4 w1 = *((const uint4*)(g_hh + (size_t)s1 * HF) + lane);
        uint4 w2 = *((const uint4*)(g_hh + (size_t)s2 * HF) + lane);
        uint4 w3 = *((const uint4*)(g_hh + (size_t)s3 * HF) + lane);

        float c_n = 0.f;
        if (more) {
            int sqn = __shfl_sync(FULL, sj_n, q);
            float en = __ldg(g_el + (size_t)sqn * HEADS + hh) + er_h;
            en = (en > 0.f) ? en : NEG_SLOPE * en;
            c_n = ((jn + q) < deg) ? __expf(en) : 0.f;
        }

#define AGG_EDGE(W, C)                                                        \
        {                                                                     \
            float2 f0 = __half22float2(*(const __half2*)&(W).x);              \
            float2 f1 = __half22float2(*(const __half2*)&(W).y);              \
            float2 f2 = __half22float2(*(const __half2*)&(W).z);              \
            float2 f3 = __half22float2(*(const __half2*)&(W).w);              \
            acc[0] = fmaf(f0.x, (C), acc[0]); acc[1] = fmaf(f0.y, (C), acc[1]); \
            acc[2] = fmaf(f1.x, (C), acc[2]); acc[3] = fmaf(f1.y, (C), acc[3]); \
            acc[4] = fmaf(f2.x, (C), acc[4]); acc[5] = fmaf(f2.y, (C), acc[5]); \
            acc[6] = fmaf(f3.x, (C), acc[6]); acc[7] = fmaf(f3.y, (C), acc[7]); \
        }
        AGG_EDGE(w0, c0) AGG_EDGE(w1, c1) AGG_EDGE(w2, c2) AGG_EDGE(w3, c3)
#undef AGG_EDGE

        sj_c = sj_n;
        c_c = c_n;
    }

    smp += __shfl_xor_sync(FULL, smp, 8);
    smp += __shfl_xor_sync(FULL, smp, 16);
    float inv = 1.0f / smp;
    float cinv = __shfl_sync(FULL, inv, gh);

    __stcs((float4*)orow + lane * 2,
           make_float4(fmaf(acc[0], cinv, bv0.x), fmaf(acc[1], cinv, bv0.y),
                       fmaf(acc[2], cinv, bv0.z), fmaf(acc[3], cinv, bv0.w)));
    __stcs((float4*)orow + lane * 2 + 1,
           make_float4(fmaf(acc[4], cinv, bv1.x), fmaf(acc[5], cinv, bv1.y),
                       fmaf(acc[6], cinv, bv1.z), fmaf(acc[7], cinv, bv1.w)));
}

// ---------------- launch (fork-join; gemm is submission index 3 for ncu capture) ----------------
static cudaStream_t get_side_stream() {
    static cudaStream_t s = [] {
        cudaStream_t t;
        cudaStreamCreateWithFlags(&t, cudaStreamNonBlocking);
        return t;
    }();
    return s;
}
static cudaEvent_t get_ev(int which) {
    static cudaEvent_t e0 = [] {
        cudaEvent_t e; cudaEventCreateWithFlags(&e, cudaEventDisableTiming); return e;
    }();
    static cudaEvent_t e1 = [] {
        cudaEvent_t e; cudaEventCreateWithFlags(&e, cudaEventDisableTiming); return e;
    }();
    return which ? e1 : e0;
}

extern "C" void kernel_launch(void* const* d_in, const int* in_sizes, int n_in,
                              void* d_out, int out_size) {
    const float* feat   = (const float*)d_in[0];
    const int*   src    = (const int*)d_in[1];
    const int*   dst    = (const int*)d_in[2];
    const float* fc_w   = (const float*)d_in[3];
    const float* attn_l = (const float*)d_in[4];
    const float* attn_r = (const float*)d_in[5];
    const float* bias   = (const float*)d_in[6];
    float* out = (float*)d_out;

    const int M = in_sizes[0] / IN_FEATS;
    const int E = in_sizes[1];

    cudaFuncSetAttribute(gemm_wmma_kernel,
                         cudaFuncAttributeMaxDynamicSharedMemorySize, GEMM_SMEM_BYTES);

    cudaStream_t sB = get_side_stream();
    cudaEvent_t evF = get_ev(0), evJ = get_ev(1);

    cudaEventRecord(evF, 0);
    cudaStreamWaitEvent(sB, evF, 0);

    // [0] main: fused fp32->fp16 convert (feat + weights)
    int n8feat = M * (IN_FEATS / 8);
    int n8all = n8feat + HF * IN_FEATS / 8;
    cvt_all_kernel<<<(n8all + 255) / 256, 256>>>(feat, fc_w, n8feat);
    // [1] side: histogram + per-edge rank
    hist_kernel<<<(E / 4 + 255) / 256, 256, 0, sB>>>(dst, E);
    // [2] side: partial sums
    int nb = (M + SCAN_CHUNK - 1) / SCAN_CHUNK;
    partial_sum_kernel<<<nb, 512, 0, sB>>>(M);
    // [3] main: tensor-core GEMM + fused el/er  (ncu capture target)
    dim3 ggrid((M + 127) / 128, HF / 128);
    gemm_wmma_kernel<<<ggrid, 256, GEMM_SMEM_BYTES>>>(attn_l, attn_r, M);
    // [4..6] side: scan + atomic-free scatter (also re-zeroes g_cnt)
    scan_blk_kernel<<<1, 32, 0, sB>>>(nb, E, M);
    scan_final_kernel<<<nb, 512, 0, sB>>>(M);
    scatter_kernel<<<(E / 4 + 255) / 256, 256, 0, sB>>>(src, dst, E, M);

    cudaEventRecord(evJ, sB);
    cudaStreamWaitEvent(0, evJ, 0);

    // [7] main: fused softmax + aggregation
    int warp_blocks = (M * 32 + 255) / 256;
    gat_agg_kernel<<<warp_blocks, 256>>>(bias, out, M);
}

// round 17
// speedup vs baseline: 1.0734x; 1.0110x over previous
#include <cuda_runtime.h>
#include <cuda_fp16.h>
#include <mma.h>
#include <math.h>
#include <cstdint>

using namespace nvcuda;

#define HEADS 8
#define OUTF 32
#define HF 256
#define IN_FEATS 256
#define NEG_SLOPE 0.2f
#define SCAN_CHUNK 4096
#define N_NODES_MAX 100000
#define N_EDGES_MAX 3200000
#define FULL 0xffffffffu

// ---------------- device scratch ----------------
__device__ __align__(16) __half g_hh[(size_t)N_NODES_MAX * HF];      // projected features, fp16
__device__ __align__(16) __half g_feat_h[(size_t)N_NODES_MAX * IN_FEATS]; // feat fp16
__device__ __align__(16) __half g_w_h[HF * IN_FEATS];                // weights fp16
__device__ float g_el[N_NODES_MAX * HEADS];
__device__ float g_er[N_NODES_MAX * HEADS];
__device__ int   g_cnt[N_NODES_MAX];          // zero at load; re-zeroed by scatter each call
__device__ int   g_row_off[N_NODES_MAX + 1];
__device__ int   g_rank[N_EDGES_MAX];         // edge rank within its dst segment
__device__ int   g_csr_src[N_EDGES_MAX];
__device__ int   g_blksum[64];
__device__ int   g_blkoff[64];

// ---------------- cp.async helpers ----------------
__device__ __forceinline__ void cp_async16(unsigned int smem_addr, const void* gptr, bool valid) {
    int sz = valid ? 16 : 0;
    asm volatile("cp.async.cg.shared.global [%0], [%1], 16, %2;"
                 :: "r"(smem_addr), "l"(gptr), "r"(sz));
}
__device__ __forceinline__ void cp_async_commit() {
    asm volatile("cp.async.commit_group;");
}

// ---------------- fused fp32 -> fp16 converter (feat then weights) ----------------
__global__ void cvt_all_kernel(const float* __restrict__ feat,
                               const float* __restrict__ W, int n8feat) {
    int i = blockIdx.x * blockDim.x + threadIdx.x;
    const float* srcp;
    __half* dstp;
    if (i < n8feat) {
        srcp = feat + (size_t)i * 8;
        dstp = g_feat_h + (size_t)i * 8;
    } else {
        int j = i - n8feat;
        if (j >= HF * IN_FEATS / 8) return;
        srcp = W + (size_t)j * 8;
        dstp = g_w_h + (size_t)j * 8;
    }
    const float4* p = (const float4*)srcp;
    float4 a = p[0], b = p[1];
    __half2 h0 = __floats2half2_rn(a.x, a.y);
    __half2 h1 = __floats2half2_rn(a.z, a.w);
    __half2 h2 = __floats2half2_rn(b.x, b.y);
    __half2 h3 = __floats2half2_rn(b.z, b.w);
    uint4 pk;
    pk.x = *(unsigned*)&h0; pk.y = *(unsigned*)&h1;
    pk.z = *(unsigned*)&h2; pk.w = *(unsigned*)&h3;
    *(uint4*)dstp = pk;
}

// ---------------- 1) HMMA GEMM (BM=128, BN=128, BK=32), 4-stage cp.async, 1 barrier/step ----------------
// 4 tile buffers (80 KB), prefetch distance 2; buffer-reuse gap of 2 iterations lets a
// single post-wait __syncthreads per K-step order reads-before-rewrites across warps.
#define TILE_HALVES (128 * 40)
#define TILE_BYTES  (TILE_HALVES * 2)
#define GEMM_SMEM_BYTES (8 * TILE_BYTES)   // 4 A-bufs + 4 B-bufs = 81920; epilogue (73728) aliases

__global__ void __launch_bounds__(256, 2) gemm_wmma_kernel(const float* __restrict__ attn_l,
                                                           const float* __restrict__ attn_r,
                                                           int M) {
    extern __shared__ char dynsmem[];
    __half* As = (__half*)dynsmem;            // [4][128][40]
    __half* Bs = As + 4 * TILE_HALVES;        // [4][128][40]
    float*  epi = (float*)dynsmem;            // reuse: [8][32][72]
    __shared__ float al_s[128], ar_s[128];

    const int m0 = blockIdx.x * 128;
    const int n0 = blockIdx.y * 128;
    const int tid = threadIdx.x;
    const int warp = tid >> 5;
    const int lane = tid & 31;
    const int wy = warp >> 1;   // 0..3 (m)
    const int wx = warp & 1;    // 0..1 (n)

    if (tid < 128) {
        al_s[tid] = attn_l[n0 + tid];
        ar_s[tid] = attn_r[n0 + tid];
    }

    // loader mapping: 512 chunks per tile per matrix; 2 per thread each
    const int idx0 = tid, idx1 = tid + 256;
    const int r0i = idx0 >> 2, q0 = idx0 & 3;
    const int r1i = idx1 >> 2, q1 = idx1 & 3;
    const bool v0 = (m0 + r0i) < M;
    const bool v1 = (m0 + r1i) < M;

    const unsigned int asm0 = (unsigned int)__cvta_generic_to_shared(As + r0i * 40 + q0 * 8);
    const unsigned int asm1 = (unsigned int)__cvta_generic_to_shared(As + r1i * 40 + q1 * 8);
    const unsigned int bsm0 = (unsigned int)__cvta_generic_to_shared(Bs + r0i * 40 + q0 * 8);
    const unsigned int bsm1 = (unsigned int)__cvta_generic_to_shared(Bs + r1i * 40 + q1 * 8);
    const __half* ga0 = g_feat_h + (size_t)(m0 + r0i) * IN_FEATS + q0 * 8;
    const __half* ga1 = g_feat_h + (size_t)(m0 + r1i) * IN_FEATS + q1 * 8;
    const __half* gb0 = g_w_h + (size_t)(n0 + r0i) * IN_FEATS + q0 * 8;
    const __half* gb1 = g_w_h + (size_t)(n0 + r1i) * IN_FEATS + q1 * 8;

    auto issue_tile = [&](int buf, int k0) {
        unsigned int off = buf * TILE_BYTES;
        cp_async16(asm0 + off, ga0 + k0, v0);
        cp_async16(asm1 + off, ga1 + k0, v1);
        cp_async16(bsm0 + off, gb0 + k0, true);
        cp_async16(bsm1 + off, gb1 + k0, true);
        cp_async_commit();
    };

    // prologue: 2 tiles in flight
    issue_tile(0, 0);
    issue_tile(1, 32);

    wmma::fragment<wmma::accumulator, 16, 16, 16, float> acc[2][4];
#pragma unroll
    for (int i = 0; i < 2; i++)
#pragma unroll
        for (int j = 0; j < 4; j++) wmma::fill_fragment(acc[i][j], 0.0f);

#pragma unroll 1
    for (int kt = 0; kt < IN_FEATS / 32; kt++) {
        // issue tile kt+2 (or an empty group to keep group counting uniform)
        int kn = (kt + 2) * 32;
        if (kn < IN_FEATS) issue_tile((kt + 2) & 3, kn);
        else cp_async_commit();

        // group kt is complete once at most 2 newer groups remain pending
        asm volatile("cp.async.wait_group 2;");
        __syncthreads();   // single barrier: data-ready + reuse protection (gap = 2 iters)

        const __half* Ab = As + (kt & 3) * TILE_HALVES;
        const __half* Bb = Bs + (kt & 3) * TILE_HALVES;
#pragma unroll
        for (int ks = 0; ks < 32; ks += 16) {
            wmma::fragment<wmma::matrix_a, 16, 16, 16, __half, wmma::row_major> fa[2];
            wmma::fragment<wmma::matrix_b, 16, 16, 16, __half, wmma::col_major> fb[4];
#pragma unroll
            for (int i = 0; i < 2; i++)
                wmma::load_matrix_sync(fa[i], Ab + (wy * 32 + i * 16) * 40 + ks, 40);
#pragma unroll
            for (int j = 0; j < 4; j++)
                wmma::load_matrix_sync(fb[j], Bb + (wx * 64 + j * 16) * 40 + ks, 40);
#pragma unroll
            for (int i = 0; i < 2; i++)
#pragma unroll
                for (int j = 0; j < 4; j++)
                    wmma::mma_sync(acc[i][j], fa[i], fb[j], acc[i][j]);
        }
    }

    // all warps done with tile smem before the epilogue aliases it
    __syncthreads();

    // ---- single-wave epilogue (80 KB smem fits all 8 warps' staging) ----
    float* ws = epi + warp * 32 * 72;
#pragma unroll
    for (int i = 0; i < 2; i++)
#pragma unroll
        for (int j = 0; j < 4; j++)
            wmma::store_matrix_sync(ws + i * 16 * 72 + j * 16, acc[i][j], 72,
                                    wmma::mem_row_major);
    __syncwarp();

    const int grow = m0 + wy * 32 + lane;
    const float* al = al_s + wx * 64;
    const float* ar = ar_s + wx * 64;
    const float* hr = ws + lane * 72;

    float el0 = 0.f, er0 = 0.f, el1 = 0.f, er1 = 0.f;
#pragma unroll
    for (int c = 0; c < 32; c++) {
        float v = hr[c];
        el0 = fmaf(v, al[c], el0);
        er0 = fmaf(v, ar[c], er0);
    }
#pragma unroll
    for (int c = 32; c < 64; c++) {
        float v = hr[c];
        el1 = fmaf(v, al[c], el1);
        er1 = fmaf(v, ar[c], er1);
    }

    if (grow < M) {
        __half* hrow = g_hh + (size_t)grow * HF + n0 + wx * 64;
#pragma unroll
        for (int c8 = 0; c8 < 8; c8++) {
            __half2 h0 = __floats2half2_rn(hr[c8 * 8 + 0], hr[c8 * 8 + 1]);
            __half2 h1 = __floats2half2_rn(hr[c8 * 8 + 2], hr[c8 * 8 + 3]);
            __half2 h2 = __floats2half2_rn(hr[c8 * 8 + 4], hr[c8 * 8 + 5]);
            __half2 h3 = __floats2half2_rn(hr[c8 * 8 + 6], hr[c8 * 8 + 7]);
            uint4 pk;
            pk.x = *(unsigned*)&h0; pk.y = *(unsigned*)&h1;
            pk.z = *(unsigned*)&h2; pk.w = *(unsigned*)&h3;
            *(uint4*)(hrow + c8 * 8) = pk;
        }
        int hb = (n0 + wx * 64) >> 5;
        g_el[(size_t)grow * HEADS + hb] = el0;
        g_el[(size_t)grow * HEADS + hb + 1] = el1;
        g_er[(size_t)grow * HEADS + hb] = er0;
        g_er[(size_t)grow * HEADS + hb + 1] = er1;
    }
}

// ---------------- 2) CSR build (rank-based, atomic-free scatter) ----------------
__global__ void hist_kernel(const int* __restrict__ dst, int E) {
    int i = (blockIdx.x * blockDim.x + threadIdx.x) * 4;
    if (i + 4 <= E) {
        int4 d = __ldcs((const int4*)(dst + i));
        int4 r;
        r.x = atomicAdd(&g_cnt[d.x], 1);
        r.y = atomicAdd(&g_cnt[d.y], 1);
        r.z = atomicAdd(&g_cnt[d.z], 1);
        r.w = atomicAdd(&g_cnt[d.w], 1);
        *(int4*)(g_rank + i) = r;
    } else {
        for (int k = i; k < E; k++) g_rank[k] = atomicAdd(&g_cnt[dst[k]], 1);
    }
}

__global__ void __launch_bounds__(512) partial_sum_kernel(int N) {
    __shared__ int wsum[16];
    int b = blockIdx.x, tid = threadIdx.x;
    int base = b * SCAN_CHUNK + tid * 8;
    int s = 0;
    if (base + 8 <= N) {
        int4 a = *(const int4*)(g_cnt + base);
        int4 c = *(const int4*)(g_cnt + base + 4);
        s = a.x + a.y + a.z + a.w + c.x + c.y + c.z + c.w;
    } else {
#pragma unroll
        for (int k = 0; k < 8; k++) { int i = base + k; if (i < N) s += g_cnt[i]; }
    }
    int lane = tid & 31, wid = tid >> 5;
#pragma unroll
    for (int d = 16; d > 0; d >>= 1) s += __shfl_xor_sync(FULL, s, d);
    if (lane == 0) wsum[wid] = s;
    __syncthreads();
    if (wid == 0) {
        int w = (lane < 16) ? wsum[lane] : 0;
#pragma unroll
        for (int d = 16; d > 0; d >>= 1) w += __shfl_xor_sync(FULL, w, d);
        if (lane == 0) g_blksum[b] = w;
    }
}

__global__ void scan_blk_kernel(int nb, int E, int N) {
    int lane = threadIdx.x;
    int v = (lane < nb) ? g_blksum[lane] : 0;
    int x = v;
#pragma unroll
    for (int d = 1; d < 32; d <<= 1) {
        int y = __shfl_up_sync(FULL, x, d);
        if (lane >= d) x += y;
    }
    if (lane < nb) g_blkoff[lane] = x - v;
    if (lane == 0) g_row_off[N] = E;
}

__global__ void __launch_bounds__(512) scan_final_kernel(int N) {
    __shared__ int wsum[16];
    __shared__ int blk_base;
    int b = blockIdx.x, tid = threadIdx.x;
    int lane = tid & 31, wid = tid >> 5;
    if (tid == 0) blk_base = g_blkoff[b];

    int base = b * SCAN_CHUNK + tid * 8;
    int v[8];
#pragma unroll
    for (int k = 0; k < 8; k++) { int i = base + k; v[k] = (i < N) ? g_cnt[i] : 0; }
    int tot = 0;
#pragma unroll
    for (int k = 0; k < 8; k++) { int t = v[k]; v[k] = tot; tot += t; }

    int x = tot;
#pragma unroll
    for (int d = 1; d < 32; d <<= 1) {
        int y = __shfl_up_sync(FULL, x, d);
        if (lane >= d) x += y;
    }
    if (lane == 31) wsum[wid] = x;
    __syncthreads();
    if (wid == 0) {
        int w = (lane < 16) ? wsum[lane] : 0;
#pragma unroll
        for (int d = 1; d < 32; d <<= 1) {
            int y = __shfl_up_sync(FULL, w, d);
            if (lane >= d) w += y;
        }
        if (lane < 16) wsum[lane] = w;
    }
    __syncthreads();
    int toff = x - tot + ((wid > 0) ? wsum[wid - 1] : 0) + blk_base;
#pragma unroll
    for (int k = 0; k < 8; k++) {
        int i = base + k;
        if (i < N) g_row_off[i] = toff + v[k];
    }
}

__global__ void scatter_kernel(const int* __restrict__ src,
                               const int* __restrict__ dst, int E, int N) {
    int t = blockIdx.x * blockDim.x + threadIdx.x;
    if (t < N) g_cnt[t] = 0;
    int i = t * 4;
    if (i + 4 <= E) {
        int4 s = __ldcs((const int4*)(src + i));
        int4 d = __ldcs((const int4*)(dst + i));
        int4 r = *(const int4*)(g_rank + i);
        g_csr_src[g_row_off[d.x] + r.x] = s.x;
        g_csr_src[g_row_off[d.y] + r.y] = s.y;
        g_csr_src[g_row_off[d.z] + r.z] = s.z;
        g_csr_src[g_row_off[d.w] + r.w] = s.w;
    } else {
        for (int k = i; k < E; k++)
            g_csr_src[g_row_off[dst[k]] + g_rank[k]] = src[k];
    }
}

// ---------------- 3) single-pass pipelined softmax + fp16 aggregation ----------------
__global__ void __launch_bounds__(256) gat_agg_kernel(const float* __restrict__ bias,
                                                      float* __restrict__ out, int N) {
    int gwarp = (blockIdx.x * blockDim.x + threadIdx.x) >> 5;
    int lane = threadIdx.x & 31;
    if (gwarp >= N) return;

    const int n = gwarp;
    const int base = g_row_off[n];
    const int deg = g_row_off[n + 1] - base;

    float* orow = out + (size_t)n * HF;
    const float4* b4 = (const float4*)bias;
    float4 bv0 = b4[lane * 2], bv1 = b4[lane * 2 + 1];

    if (deg == 0) {
        __stcs((float4*)orow + lane * 2, bv0);
        __stcs((float4*)orow + lane * 2 + 1, bv1);
        return;
    }

    const int lane3 = lane & 3;
    const int hh = lane & 7;
    const int q = lane >> 3;
    const int gh = lane >> 2;
    const float er_h = __ldg(g_er + (size_t)n * HEADS + hh);

    float acc[8];
#pragma unroll
    for (int j = 0; j < 8; j++) acc[j] = 0.f;
    float smp = 0.f;

    int sj_c;
    {
        int i4 = lane3;
        sj_c = __ldcs(g_csr_src + base + ((i4 < deg) ? i4 : (deg - 1)));
    }
    float c_c;
    {
        int sq = __shfl_sync(FULL, sj_c, q);
        float e = __ldg(g_el + (size_t)sq * HEADS + hh) + er_h;
        e = (e > 0.f) ? e : NEG_SLOPE * e;
        c_c = (q < deg) ? __expf(e) : 0.f;
    }

    for (int j = 0; j < deg; j += 4) {
        const int jn = j + 4;
        const bool more = jn < deg;

        int sj_n = 0;
        if (more) {
            int i4 = jn + lane3;
            sj_n = __ldcs(g_csr_src + base + ((i4 < deg) ? i4 : (deg - 1)));
        }

        int s0 = __shfl_sync(FULL, sj_c, 0);
        int s1 = __shfl_sync(FULL, sj_c, 1);
        int s2 = __shfl_sync(FULL, sj_c, 2);
        int s3 = __shfl_sync(FULL, sj_c, 3);
        float c0 = __shfl_sync(FULL, c_c, gh);
        float c1 = __shfl_sync(FULL, c_c, 8 + gh);
        float c2 = __shfl_sync(FULL, c_c, 16 + gh);
        float c3 = __shfl_sync(FULL, c_c, 24 + gh);
        smp += c_c;

        uint4 w0 = *((const uint4*)(g_hh + (size_t)s0 * HF) + lane);
        uint4 w1 = *((const uint4*)(g_hh + (size_t)s1 * HF) + lane);
        uint4 w2 = *((const uint4*)(g_hh + (size_t)s2 * HF) + lane);
        uint4 w3 = *((const uint4*)(g_hh + (size_t)s3 * HF) + lane);

        float c_n = 0.f;
        if (more) {
            int sqn = __shfl_sync(FULL, sj_n, q);
            float en = __ldg(g_el + (size_t)sqn * HEADS + hh) + er_h;
            en = (en > 0.f) ? en : NEG_SLOPE * en;
            c_n = ((jn + q) < deg) ? __expf(en) : 0.f;
        }

#define AGG_EDGE(W, C)                                                        \
        {                                                                     \
            float2 f0 = __half22float2(*(const __half2*)&(W).x);              \
            float2 f1 = __half22float2(*(const __half2*)&(W).y);              \
            float2 f2 = __half22float2(*(const __half2*)&(W).z);              \
            float2 f3 = __half22float2(*(const __half2*)&(W).w);              \
            acc[0] = fmaf(f0.x, (C), acc[0]); acc[1] = fmaf(f0.y, (C), acc[1]); \
            acc[2] = fmaf(f1.x, (C), acc[2]); acc[3] = fmaf(f1.y, (C), acc[3]); \
            acc[4] = fmaf(f2.x, (C), acc[4]); acc[5] = fmaf(f2.y, (C), acc[5]); \
            acc[6] = fmaf(f3.x, (C), acc[6]); acc[7] = fmaf(f3.y, (C), acc[7]); \
        }
        AGG_EDGE(w0, c0) AGG_EDGE(w1, c1) AGG_EDGE(w2, c2) AGG_EDGE(w3, c3)
#undef AGG_EDGE

        sj_c = sj_n;
        c_c = c_n;
    }

    smp += __shfl_xor_sync(FULL, smp, 8);
    smp += __shfl_xor_sync(FULL, smp, 16);
    float inv = 1.0f / smp;
    float cinv = __shfl_sync(FULL, inv, gh);

    __stcs((float4*)orow + lane * 2,
           make_float4(fmaf(acc[0], cinv, bv0.x), fmaf(acc[1], cinv, bv0.y),
                       fmaf(acc[2], cinv, bv0.z), fmaf(acc[3], cinv, bv0.w)));
    __stcs((float4*)orow + lane * 2 + 1,
           make_float4(fmaf(acc[4], cinv, bv1.x), fmaf(acc[5], cinv, bv1.y),
                       fmaf(acc[6], cinv, bv1.z), fmaf(acc[7], cinv, bv1.w)));
}

// ---------------- launch (fork-join; gemm is submission index 3 for ncu capture) ----------------
static cudaStream_t get_side_stream() {
    static cudaStream_t s = [] {
        cudaStream_t t;
        cudaStreamCreateWithFlags(&t, cudaStreamNonBlocking);
        return t;
    }();
    return s;
}
static cudaEvent_t get_ev(int which) {
    static cudaEvent_t e0 = [] {
        cudaEvent_t e; cudaEventCreateWithFlags(&e, cudaEventDisableTiming); return e;
    }();
    static cudaEvent_t e1 = [] {
        cudaEvent_t e; cudaEventCreateWithFlags(&e, cudaEventDisableTiming); return e;
    }();
    return which ? e1 : e0;
}

extern "C" void kernel_launch(void* const* d_in, const int* in_sizes, int n_in,
                              void* d_out, int out_size) {
    const float* feat   = (const float*)d_in[0];
    const int*   src    = (const int*)d_in[1];
    const int*   dst    = (const int*)d_in[2];
    const float* fc_w   = (const float*)d_in[3];
    const float* attn_l = (const float*)d_in[4];
    const float* attn_r = (const float*)d_in[5];
    const float* bias   = (const float*)d_in[6];
    float* out = (float*)d_out;

    const int M = in_sizes[0] / IN_FEATS;
    const int E = in_sizes[1];

    cudaFuncSetAttribute(gemm_wmma_kernel,
                         cudaFuncAttributeMaxDynamicSharedMemorySize, GEMM_SMEM_BYTES);

    cudaStream_t sB = get_side_stream();
    cudaEvent_t evF = get_ev(0), evJ = get_ev(1);

    cudaEventRecord(evF, 0);
    cudaStreamWaitEvent(sB, evF, 0);

    // [0] main: fused fp32->fp16 convert (feat + weights)
    int n8feat = M * (IN_FEATS / 8);
    int n8all = n8feat + HF * IN_FEATS / 8;
    cvt_all_kernel<<<(n8all + 255) / 256, 256>>>(feat, fc_w, n8feat);
    // [1] side: histogram + per-edge rank
    hist_kernel<<<(E / 4 + 255) / 256, 256, 0, sB>>>(dst, E);
    // [2] side: partial sums
    int nb = (M + SCAN_CHUNK - 1) / SCAN_CHUNK;
    partial_sum_kernel<<<nb, 512, 0, sB>>>(M);
    // [3] main: tensor-core GEMM + fused el/er  (ncu capture target)
    dim3 ggrid((M + 127) / 128, HF / 128);
    gemm_wmma_kernel<<<ggrid, 256, GEMM_SMEM_BYTES>>>(attn_l, attn_r, M);
    // [4..6] side: scan + atomic-free scatter (also re-zeroes g_cnt)
    scan_blk_kernel<<<1, 32, 0, sB>>>(nb, E, M);
    scan_final_kernel<<<nb, 512, 0, sB>>>(M);
    scatter_kernel<<<(E / 4 + 255) / 256, 256, 0, sB>>>(src, dst, E, M);

    cudaEventRecord(evJ, sB);
    cudaStreamWaitEvent(0, evJ, 0);

    // [7] main: fused softmax + aggregation
    int warp_blocks = (M * 32 + 255) / 256;
    gat_agg_kernel<<<warp_blocks, 256>>>(bias, out, M);
}